// round 3
// baseline (speedup 1.0000x reference)
#include <cuda_runtime.h>
#include <math.h>

#define N 512
#define C 1024
#define HREP 256
#define HID 256
#define HEADS 4
#define NCLS 91
#define KNBR 5
#define MAXDEG 520

// ---------------- scratch (device globals; NEVER passed as launch args) ----------
__device__ float g_p1[N * HREP];           // p1 + b1, [n][h]
__device__ float g_p2t[HREP * N];          // p2 transposed, [h][n]
__device__ int   g_nbrs[N * KNBR];
__device__ int   g_adj[N * MAXDEG];
__device__ int   g_cnt[N];
__device__ float g_x[N * 1028];            // concat(feats, geom)
__device__ float g_h[N * 1024];            // gat1 linear out
__device__ float g_as1[N * HEADS];
__device__ float g_ad1[N * HEADS];
__device__ float g_alpha1[N * MAXDEG * HEADS];
__device__ float g_h1[N * 1024];           // relu(gat1 out + b)
__device__ float g_h2[N * NCLS];           // gat2 linear out
__device__ float g_as2[N];
__device__ float g_ad2[N];
__device__ float g_alpha2[N * MAXDEG];

// ---------------- NT GEMM 64x64 tile, 4x4/thread ---------------------------------
// MODE 0: g_p1[n*256+h] = sum_k feats[n,k]*W[h*2052+k] + bias[h]
// MODE 1: g_p2t[h*512+n] = sum_k feats[n,k]*W[h*2052+1024+k]
template<int MODE>
__global__ void gemm_nt64(const float* __restrict__ A, const float* __restrict__ W,
                          const float* __restrict__ bias)
{
    __shared__ float As[16][64];
    __shared__ float Ws[16][64];
    const int tx = threadIdx.x, ty = threadIdx.y;
    const int tid = ty * 16 + tx;
    const int n0 = blockIdx.x * 64, h0 = blockIdx.y * 64;
    const int lr = tid >> 2;          // 0..63
    const int lk = (tid & 3) * 4;     // 0,4,8,12
    const int woff = (MODE == 0) ? 0 : 1024;

    float acc[4][4];
#pragma unroll
    for (int i = 0; i < 4; i++)
#pragma unroll
        for (int j = 0; j < 4; j++) acc[i][j] = 0.f;

    for (int k0 = 0; k0 < C; k0 += 16) {
        float4 av = *reinterpret_cast<const float4*>(&A[(size_t)(n0 + lr) * C + k0 + lk]);
        As[lk + 0][lr] = av.x; As[lk + 1][lr] = av.y;
        As[lk + 2][lr] = av.z; As[lk + 3][lr] = av.w;
        float4 wv = *reinterpret_cast<const float4*>(&W[(size_t)(h0 + lr) * 2052 + woff + k0 + lk]);
        Ws[lk + 0][lr] = wv.x; Ws[lk + 1][lr] = wv.y;
        Ws[lk + 2][lr] = wv.z; Ws[lk + 3][lr] = wv.w;
        __syncthreads();
#pragma unroll
        for (int kk = 0; kk < 16; kk++) {
            float4 a4 = *reinterpret_cast<float4*>(&As[kk][ty * 4]);
            float4 b4 = *reinterpret_cast<float4*>(&Ws[kk][tx * 4]);
            float ar[4] = {a4.x, a4.y, a4.z, a4.w};
            float br[4] = {b4.x, b4.y, b4.z, b4.w};
#pragma unroll
            for (int i = 0; i < 4; i++)
#pragma unroll
                for (int j = 0; j < 4; j++) acc[i][j] += ar[i] * br[j];
        }
        __syncthreads();
    }

#pragma unroll
    for (int j = 0; j < 4; j++) {
        const int h = h0 + tx * 4 + j;
        const float bv = (MODE == 0) ? bias[h] : 0.f;
#pragma unroll
        for (int i = 0; i < 4; i++) {
            const int n = n0 + ty * 4 + i;
            const float v = acc[i][j] + bv;
            if (MODE == 0) g_p1[(size_t)n * HREP + h] = v;
            else           g_p2t[(size_t)h * N + n] = v;
        }
    }
}

// ---------------- GAT1 linear: g_h = g_x(512x1028) @ gat1_w(1028x1024) -----------
// Main loop over K=1024, geom tail (cols 1024..1027) added at writeback.
__global__ void gemm_nn_gat1(const float* __restrict__ B)
{
    __shared__ float As[16][64];
    __shared__ float Bs[16][64];
    const int tx = threadIdx.x, ty = threadIdx.y;
    const int tid = ty * 16 + tx;
    const int n0 = blockIdx.x * 64, o0 = blockIdx.y * 64;
    const int lr = tid >> 2;
    const int lk = (tid & 3) * 4;
    const int kb = tid >> 4;          // 0..15
    const int cg = (tid & 15) * 4;    // 0..60

    float acc[4][4];
#pragma unroll
    for (int i = 0; i < 4; i++)
#pragma unroll
        for (int j = 0; j < 4; j++) acc[i][j] = 0.f;

    for (int k0 = 0; k0 < 1024; k0 += 16) {
        float4 av = *reinterpret_cast<const float4*>(&g_x[(size_t)(n0 + lr) * 1028 + k0 + lk]);
        As[lk + 0][lr] = av.x; As[lk + 1][lr] = av.y;
        As[lk + 2][lr] = av.z; As[lk + 3][lr] = av.w;
        float4 bv = *reinterpret_cast<const float4*>(&B[(size_t)(k0 + kb) * 1024 + o0 + cg]);
        *reinterpret_cast<float4*>(&Bs[kb][cg]) = bv;
        __syncthreads();
#pragma unroll
        for (int kk = 0; kk < 16; kk++) {
            float4 a4 = *reinterpret_cast<float4*>(&As[kk][ty * 4]);
            float4 b4 = *reinterpret_cast<float4*>(&Bs[kk][tx * 4]);
            float ar[4] = {a4.x, a4.y, a4.z, a4.w};
            float br[4] = {b4.x, b4.y, b4.z, b4.w};
#pragma unroll
            for (int i = 0; i < 4; i++)
#pragma unroll
                for (int j = 0; j < 4; j++) acc[i][j] += ar[i] * br[j];
        }
        __syncthreads();
    }

#pragma unroll
    for (int j = 0; j < 4; j++) {
        const int col = o0 + tx * 4 + j;
        const float w0 = B[(size_t)1024 * 1024 + col];
        const float w1 = B[(size_t)1025 * 1024 + col];
        const float w2 = B[(size_t)1026 * 1024 + col];
        const float w3 = B[(size_t)1027 * 1024 + col];
#pragma unroll
        for (int i = 0; i < 4; i++) {
            const int n = n0 + ty * 4 + i;
            float v = acc[i][j]
                    + g_x[(size_t)n * 1028 + 1024] * w0 + g_x[(size_t)n * 1028 + 1025] * w1
                    + g_x[(size_t)n * 1028 + 1026] * w2 + g_x[(size_t)n * 1028 + 1027] * w3;
            g_h[(size_t)n * 1024 + col] = v;
        }
    }
}

// ---------------- GAT2 linear: g_h2 = g_h1(512x1024) @ gat2_w(1024x91) -----------
__global__ void gemm_gat2(const float* __restrict__ B)
{
    __shared__ float As[16][17];
    __shared__ float Bs[16][17];
    const int tx = threadIdx.x, ty = threadIdx.y;
    const int n = blockIdx.y * 16 + ty;
    const int o = blockIdx.x * 16 + tx;
    float acc = 0.f;
    for (int k0 = 0; k0 < 1024; k0 += 16) {
        As[ty][tx] = g_h1[(size_t)n * 1024 + k0 + tx];
        Bs[ty][tx] = (o < NCLS) ? B[(size_t)(k0 + ty) * NCLS + o] : 0.f;
        __syncthreads();
#pragma unroll
        for (int kk = 0; kk < 16; kk++)
            acc += As[ty][kk] * Bs[kk][tx];
        __syncthreads();
    }
    if (o < NCLS)
        g_h2[(size_t)n * NCLS + o] = acc;
}

// ---------------- rel[i][j] -------------------------------------------------------
__global__ void rel_simple(const float* __restrict__ boxes,
                           const float* __restrict__ w1,    // repn_w1, ld 2052, wg at col 2048
                           const float* __restrict__ w2,
                           const float* __restrict__ b2,
                           float* __restrict__ rel)
{
    __shared__ float p1s[HREP];
    __shared__ float w2s[HREP];
    __shared__ float wgs[HREP * 4];
    const int i = blockIdx.x;
    const int j = threadIdx.x;                   // 512
    if (j < HREP) { p1s[j] = g_p1[i * HREP + j]; w2s[j] = w2[j]; }
    for (int t = j; t < HREP * 4; t += 512)
        wgs[t] = w1[(size_t)(t >> 2) * 2052 + 2048 + (t & 3)];
    __syncthreads();

    const float g0 = fabsf(boxes[i * 4 + 0] - boxes[j * 4 + 0]);
    const float g1 = fabsf(boxes[i * 4 + 1] - boxes[j * 4 + 1]);
    const float g2 = fabsf(boxes[i * 4 + 2] - boxes[j * 4 + 2]);
    const float g3 = fabsf(boxes[i * 4 + 3] - boxes[j * 4 + 3]);

    float acc = 0.f;
    for (int h = 0; h < HREP; h++) {
        float v = p1s[h] + g_p2t[h * N + j]
                + g0 * wgs[h * 4 + 0] + g1 * wgs[h * 4 + 1]
                + g2 * wgs[h * 4 + 2] + g3 * wgs[h * 4 + 3];
        acc += fmaxf(v, 0.f) * w2s[h];
    }
    rel[(size_t)i * N + j] = acc + b2[0];
}

// ---------------- top-(k+1) per row (1 warp/row), drop rank-1 --------------------
__global__ void topk_warp(const float* __restrict__ rel)
{
    const int i = blockIdx.x;
    const int lane = threadIdx.x;                // 32
    float v[16];
#pragma unroll
    for (int q = 0; q < 16; q++)
        v[q] = rel[(size_t)i * N + q * 32 + lane];

    for (int r = 0; r < KNBR + 1; r++) {
        float bv = -INFINITY; int bidx = 0x7fffffff;
#pragma unroll
        for (int q = 0; q < 16; q++) {
            if (v[q] > bv) { bv = v[q]; bidx = q * 32 + lane; }
        }
#pragma unroll
        for (int o = 16; o > 0; o >>= 1) {
            float ov = __shfl_down_sync(0xffffffffu, bv, o);
            int   oi = __shfl_down_sync(0xffffffffu, bidx, o);
            if (ov > bv || (ov == bv && oi < bidx)) { bv = ov; bidx = oi; }
        }
        bidx = __shfl_sync(0xffffffffu, bidx, 0);
        if (r > 0 && lane == 0) g_nbrs[i * KNBR + r - 1] = bidx;
        if ((bidx & 31) == lane) v[bidx >> 5] = -INFINITY;
    }
}

// ---------------- adjacency: fully serial per dst --------------------------------
__global__ void adj_simple()
{
    int d = blockIdx.x * blockDim.x + threadIdx.x;
    if (d >= N) return;
    int c = 0;
    for (int i = 0; i < N; i++) {
#pragma unroll
        for (int j = 0; j < KNBR; j++)
            if (g_nbrs[i * KNBR + j] == d) g_adj[d * MAXDEG + c++] = i;
    }
    g_adj[d * MAXDEG + c++] = d;   // self loop
    g_cnt[d] = c;
}

// ---------------- build x = concat(feats, geom) ----------------------------------
__global__ void build_x(const float* __restrict__ feats,
                        const float* __restrict__ boxes)
{
    int t = blockIdx.x * 256 + threadIdx.x;
    if (t >= N * 1028) return;
    int n = t / 1028, f = t % 1028;
    if (f < 1024) {
        g_x[t] = feats[(size_t)n * 1024 + f];
    } else {
        int d2 = f - 1024;
        float b0 = boxes[n * 4 + 0], b1 = boxes[n * 4 + 1];
        float b2v = boxes[n * 4 + 2], b3 = boxes[n * 4 + 3];
        float v;
        if (d2 == 0)      v = b0 / 800.f;
        else if (d2 == 1) v = b1 / 800.f;
        else if (d2 == 2) v = (b2v - b0) / 800.f;
        else              v = (b3 - b1) / 800.f;
        g_x[t] = v;
    }
}

// ---------------- attention projections ------------------------------------------
__global__ void aproj1(const float* __restrict__ asrc, const float* __restrict__ adst)
{
    const int n = blockIdx.x;
    const int w = threadIdx.y;     // head
    const int lane = threadIdx.x;  // 32
    float s = 0.f, dsum = 0.f;
    for (int f = lane; f < HID; f += 32) {
        float hv = g_h[(size_t)n * 1024 + w * HID + f];
        s    += hv * asrc[w * HID + f];
        dsum += hv * adst[w * HID + f];
    }
#pragma unroll
    for (int o = 16; o > 0; o >>= 1) {
        s    += __shfl_xor_sync(0xffffffffu, s, o);
        dsum += __shfl_xor_sync(0xffffffffu, dsum, o);
    }
    if (lane == 0) { g_as1[n * HEADS + w] = s; g_ad1[n * HEADS + w] = dsum; }
}

__global__ void aproj2(const float* __restrict__ asrc, const float* __restrict__ adst)
{
    const int n = blockIdx.x;
    const int lane = threadIdx.x;  // 32
    float s = 0.f, dsum = 0.f;
    for (int f = lane; f < NCLS; f += 32) {
        float v = g_h2[n * NCLS + f];
        s    += v * asrc[f];
        dsum += v * adst[f];
    }
#pragma unroll
    for (int o = 16; o > 0; o >>= 1) {
        s    += __shfl_xor_sync(0xffffffffu, s, o);
        dsum += __shfl_xor_sync(0xffffffffu, dsum, o);
    }
    if (lane == 0) { g_as2[n] = s; g_ad2[n] = dsum; }
}

// ---------------- edge alphas ----------------------------------------------------
__global__ void alpha1_kernel()
{
    const int d = blockIdx.x;
    const int lane = threadIdx.x;  // 32
    const int cnt = g_cnt[d];
    for (int hd = 0; hd < HEADS; hd++) {
        const float add = g_ad1[d * HEADS + hd];
        float lm = -INFINITY;
        for (int x = lane; x < cnt; x += 32) {
            int s = g_adj[d * MAXDEG + x];
            float a = g_as1[s * HEADS + hd] + add;
            float e = a > 0.f ? a : 0.2f * a;
            g_alpha1[(size_t)(d * MAXDEG + x) * HEADS + hd] = e;
            lm = fmaxf(lm, e);
        }
#pragma unroll
        for (int o = 16; o > 0; o >>= 1)
            lm = fmaxf(lm, __shfl_xor_sync(0xffffffffu, lm, o));
        float ls = 0.f;
        for (int x = lane; x < cnt; x += 32) {
            float e = expf(g_alpha1[(size_t)(d * MAXDEG + x) * HEADS + hd] - lm);
            g_alpha1[(size_t)(d * MAXDEG + x) * HEADS + hd] = e;
            ls += e;
        }
#pragma unroll
        for (int o = 16; o > 0; o >>= 1)
            ls += __shfl_xor_sync(0xffffffffu, ls, o);
        const float inv = 1.f / (ls + 1e-16f);
        for (int x = lane; x < cnt; x += 32)
            g_alpha1[(size_t)(d * MAXDEG + x) * HEADS + hd] *= inv;
    }
}

__global__ void alpha2_kernel()
{
    const int d = blockIdx.x;
    const int lane = threadIdx.x;  // 32
    const int cnt = g_cnt[d];
    const float add = g_ad2[d];
    float lm = -INFINITY;
    for (int x = lane; x < cnt; x += 32) {
        int s = g_adj[d * MAXDEG + x];
        float a = g_as2[s] + add;
        float e = a > 0.f ? a : 0.2f * a;
        g_alpha2[d * MAXDEG + x] = e;
        lm = fmaxf(lm, e);
    }
#pragma unroll
    for (int o = 16; o > 0; o >>= 1)
        lm = fmaxf(lm, __shfl_xor_sync(0xffffffffu, lm, o));
    float ls = 0.f;
    for (int x = lane; x < cnt; x += 32) {
        float e = expf(g_alpha2[d * MAXDEG + x] - lm);
        g_alpha2[d * MAXDEG + x] = e;
        ls += e;
    }
#pragma unroll
    for (int o = 16; o > 0; o >>= 1)
        ls += __shfl_xor_sync(0xffffffffu, ls, o);
    const float inv = 1.f / (ls + 1e-16f);
    for (int x = lane; x < cnt; x += 32)
        g_alpha2[d * MAXDEG + x] *= inv;
}

// ---------------- GAT1 weighted aggregation + bias + relu ------------------------
__global__ void gat1_out(const float* __restrict__ bias)
{
    const int d = blockIdx.x;
    const int t = threadIdx.x;     // 1024: t = hd*256 + f
    const int hd = t >> 8;
    const int cnt = g_cnt[d];
    float acc = 0.f;
    for (int x = 0; x < cnt; x++) {
        int s = g_adj[d * MAXDEG + x];
        acc += g_alpha1[(size_t)(d * MAXDEG + x) * HEADS + hd] * g_h[(size_t)s * 1024 + t];
    }
    float o = acc + bias[t];
    g_h1[(size_t)d * 1024 + t] = fmaxf(o, 0.f);
}

// ---------------- GAT2 aggregation + bias + softmax ------------------------------
__global__ void gat2_out(const float* __restrict__ bias, float* __restrict__ out)
{
    __shared__ float lrow[NCLS];
    __shared__ float red[128];
    const int d = blockIdx.x;
    const int t = threadIdx.x;     // 128
    const int cnt = g_cnt[d];
    if (t < NCLS) {
        float acc = 0.f;
        for (int x = 0; x < cnt; x++) {
            int s = g_adj[d * MAXDEG + x];
            acc += g_alpha2[d * MAXDEG + x] * g_h2[s * NCLS + t];
        }
        float lg = acc + bias[t];
        lrow[t] = lg;
        out[(size_t)d * NCLS + t] = lg;          // logits
    }
    __syncthreads();

    float v = (t < NCLS) ? lrow[t] : -INFINITY;
    red[t] = v; __syncthreads();
    for (int s = 64; s > 0; s >>= 1) {
        if (t < s) red[t] = fmaxf(red[t], red[t + s]);
        __syncthreads();
    }
    const float mx = red[0]; __syncthreads();
    float e = (t < NCLS) ? expf(lrow[t] - mx) : 0.f;
    red[t] = e; __syncthreads();
    for (int s = 64; s > 0; s >>= 1) {
        if (t < s) red[t] += red[t + s];
        __syncthreads();
    }
    const float ssum = red[0];
    if (t < NCLS)
        out[(size_t)N * NCLS + (size_t)d * NCLS + t] = e / ssum;   // probs
}

// ---------------- launch ---------------------------------------------------------
extern "C" void kernel_launch(void* const* d_in, const int* in_sizes, int n_in,
                              void* d_out, int out_size)
{
    (void)in_sizes; (void)n_in; (void)out_size;
    const float* feats     = (const float*)d_in[0];
    const float* boxes     = (const float*)d_in[1];
    const float* repn_w1   = (const float*)d_in[2];
    const float* repn_b1   = (const float*)d_in[3];
    const float* repn_w2   = (const float*)d_in[4];
    const float* repn_b2   = (const float*)d_in[5];
    const float* gat1_w    = (const float*)d_in[6];
    const float* gat1_asrc = (const float*)d_in[7];
    const float* gat1_adst = (const float*)d_in[8];
    const float* gat1_b    = (const float*)d_in[9];
    const float* gat2_w    = (const float*)d_in[10];
    const float* gat2_asrc = (const float*)d_in[11];
    const float* gat2_adst = (const float*)d_in[12];
    const float* gat2_b    = (const float*)d_in[13];
    float* out = (float*)d_out;
    float* rel_out = out + 2 * N * NCLS;

    dim3 t16(16, 16);
    gemm_nt64<0><<<dim3(8, 4), t16>>>(feats, repn_w1, repn_b1);   // g_p1
    gemm_nt64<1><<<dim3(8, 4), t16>>>(feats, repn_w1, nullptr);   // g_p2t
    rel_simple<<<N, 512>>>(boxes, repn_w1, repn_w2, repn_b2, rel_out);
    topk_warp<<<N, 32>>>(rel_out);
    adj_simple<<<2, 256>>>();
    build_x<<<(N * 1028 + 255) / 256, 256>>>(feats, boxes);
    gemm_nn_gat1<<<dim3(8, 16), t16>>>(gat1_w);                   // g_h
    aproj1<<<N, dim3(32, 4)>>>(gat1_asrc, gat1_adst);
    alpha1_kernel<<<N, 32>>>();
    gat1_out<<<N, 1024>>>(gat1_b);
    gemm_gat2<<<dim3(6, 32), t16>>>(gat2_w);                      // g_h2
    aproj2<<<N, 32>>>(gat2_asrc, gat2_adst);
    alpha2_kernel<<<N, 32>>>();
    gat2_out<<<N, 128>>>(gat2_b, out);
}

// round 4
// speedup vs baseline: 2.2519x; 2.2519x over previous
#include <cuda_runtime.h>
#include <math.h>

#define N 512
#define C 1024
#define HREP 256
#define HID 256
#define HEADS 4
#define NCLS 91
#define KNBR 5
#define MAXDEG 520

// ---------------- scratch (device globals; NEVER passed as launch args) ----------
__device__ float g_p1[N * HREP];           // p1 + b1, [n][h]
__device__ float g_p2t[HREP * N];          // p2 transposed, [h][n]
__device__ int   g_nbrs[N * KNBR];
__device__ int   g_adj[N * MAXDEG];
__device__ int   g_cnt[N];
__device__ float g_h[N * 1024];            // gat1 linear out
__device__ float g_as1[N * HEADS];
__device__ float g_ad1[N * HEADS];
__device__ float g_h1[N * 1024];           // relu(gat1 out + b)
__device__ float g_h2[N * NCLS];           // gat2 linear out
__device__ float g_as2[N];
__device__ float g_ad2[N];

// ================= fused p1/p2 NT GEMM, 32x64 tile, 2x4/thread ===================
// blockIdx.y < 4 : p1 block  -> g_p1[n*256 + h] = feats·wf1[h] + b1[h]
// blockIdx.y >= 4: p2t block -> g_p2t[h*512 + n] = feats·wf2[h]
__global__ void gemm_nt_fused(const float* __restrict__ A, const float* __restrict__ W,
                              const float* __restrict__ bias)
{
    __shared__ float As[16][32];
    __shared__ float Ws[16][64];
    const int tid = threadIdx.x;                 // 256
    const int n0 = blockIdx.x * 32;
    const int cb = blockIdx.y;
    const bool p2mode = (cb >= 4);
    const int h0 = (p2mode ? cb - 4 : cb) * 64;
    const int woff = p2mode ? 1024 : 0;
    const int ar = tid >> 3, ak = (tid & 7) * 2;   // A: 32 rows x 16k, float2 each
    const int wr = tid >> 2, wk = (tid & 3) * 4;   // W: 64 rows x 16k, float4 each
    const int tx = tid & 15, ty = tid >> 4;

    float acc[2][4];
#pragma unroll
    for (int i = 0; i < 2; i++)
#pragma unroll
        for (int j = 0; j < 4; j++) acc[i][j] = 0.f;

    for (int k0 = 0; k0 < C; k0 += 16) {
        float2 av = *reinterpret_cast<const float2*>(&A[(size_t)(n0 + ar) * C + k0 + ak]);
        As[ak][ar] = av.x; As[ak + 1][ar] = av.y;
        float4 wv = *reinterpret_cast<const float4*>(&W[(size_t)(h0 + wr) * 2052 + woff + k0 + wk]);
        Ws[wk + 0][wr] = wv.x; Ws[wk + 1][wr] = wv.y;
        Ws[wk + 2][wr] = wv.z; Ws[wk + 3][wr] = wv.w;
        __syncthreads();
#pragma unroll
        for (int kk = 0; kk < 16; kk++) {
            float a0 = As[kk][ty * 2 + 0];
            float a1 = As[kk][ty * 2 + 1];
            float4 b4 = *reinterpret_cast<float4*>(&Ws[kk][tx * 4]);
            float br[4] = {b4.x, b4.y, b4.z, b4.w};
#pragma unroll
            for (int j = 0; j < 4; j++) {
                acc[0][j] += a0 * br[j];
                acc[1][j] += a1 * br[j];
            }
        }
        __syncthreads();
    }

#pragma unroll
    for (int j = 0; j < 4; j++) {
        const int h = h0 + tx * 4 + j;
        const float bv = p2mode ? 0.f : bias[h];
#pragma unroll
        for (int i = 0; i < 2; i++) {
            const int n = n0 + ty * 2 + i;
            const float v = acc[i][j] + bv;
            if (p2mode) g_p2t[(size_t)h * N + n] = v;
            else        g_p1[(size_t)n * HREP + h] = v;
        }
    }
}

// ================= GAT1 linear: g_h = [feats|geom](512x1028) @ gat1_w ============
// 64x64 tile, 4x4/thread; K main loop over feats (1024), geom tail inline.
__global__ void gemm_nn_gat1(const float* __restrict__ A, const float* __restrict__ boxes,
                             const float* __restrict__ B)
{
    __shared__ float As[16][64];
    __shared__ float Bs[16][64];
    const int tx = threadIdx.x, ty = threadIdx.y;
    const int tid = ty * 16 + tx;
    const int n0 = blockIdx.x * 64, o0 = blockIdx.y * 64;
    const int lr = tid >> 2;
    const int lk = (tid & 3) * 4;
    const int kb = tid >> 4;
    const int cg = (tid & 15) * 4;

    float acc[4][4];
#pragma unroll
    for (int i = 0; i < 4; i++)
#pragma unroll
        for (int j = 0; j < 4; j++) acc[i][j] = 0.f;

    for (int k0 = 0; k0 < 1024; k0 += 16) {
        float4 av = *reinterpret_cast<const float4*>(&A[(size_t)(n0 + lr) * 1024 + k0 + lk]);
        As[lk + 0][lr] = av.x; As[lk + 1][lr] = av.y;
        As[lk + 2][lr] = av.z; As[lk + 3][lr] = av.w;
        float4 bv = *reinterpret_cast<const float4*>(&B[(size_t)(k0 + kb) * 1024 + o0 + cg]);
        *reinterpret_cast<float4*>(&Bs[kb][cg]) = bv;
        __syncthreads();
#pragma unroll
        for (int kk = 0; kk < 16; kk++) {
            float4 a4 = *reinterpret_cast<float4*>(&As[kk][ty * 4]);
            float4 b4 = *reinterpret_cast<float4*>(&Bs[kk][tx * 4]);
            float ar[4] = {a4.x, a4.y, a4.z, a4.w};
            float br[4] = {b4.x, b4.y, b4.z, b4.w};
#pragma unroll
            for (int i = 0; i < 4; i++)
#pragma unroll
                for (int j = 0; j < 4; j++) acc[i][j] += ar[i] * br[j];
        }
        __syncthreads();
    }

#pragma unroll
    for (int j = 0; j < 4; j++) {
        const int col = o0 + tx * 4 + j;
        const float w0 = B[(size_t)1024 * 1024 + col];
        const float w1 = B[(size_t)1025 * 1024 + col];
        const float w2 = B[(size_t)1026 * 1024 + col];
        const float w3 = B[(size_t)1027 * 1024 + col];
#pragma unroll
        for (int i = 0; i < 4; i++) {
            const int n = n0 + ty * 4 + i;
            const float b0 = boxes[n * 4 + 0], b1 = boxes[n * 4 + 1];
            const float b2v = boxes[n * 4 + 2], b3 = boxes[n * 4 + 3];
            const float gm0 = b0 / 800.f, gm1 = b1 / 800.f;
            const float gm2 = (b2v - b0) / 800.f, gm3 = (b3 - b1) / 800.f;
            float v = acc[i][j] + gm0 * w0 + gm1 * w1 + gm2 * w2 + gm3 * w3;
            g_h[(size_t)n * 1024 + col] = v;
        }
    }
}

// ================= GAT2 linear: g_h2 = g_h1(512x1024) @ gat2_w(1024x91) ==========
__global__ void gemm_gat2(const float* __restrict__ B)
{
    __shared__ float As[16][17];
    __shared__ float Bs[16][17];
    const int tx = threadIdx.x, ty = threadIdx.y;
    const int n = blockIdx.y * 16 + ty;
    const int o = blockIdx.x * 16 + tx;
    float acc = 0.f;
    for (int k0 = 0; k0 < 1024; k0 += 16) {
        As[ty][tx] = g_h1[(size_t)n * 1024 + k0 + tx];
        Bs[ty][tx] = (o < NCLS) ? B[(size_t)(k0 + ty) * NCLS + o] : 0.f;
        __syncthreads();
#pragma unroll
        for (int kk = 0; kk < 16; kk++)
            acc += As[ty][kk] * Bs[kk][tx];
        __syncthreads();
    }
    if (o < NCLS)
        g_h2[(size_t)n * NCLS + o] = acc;
}

// ================= rel with 4-row i-tiling ========================================
__global__ void rel4(const float* __restrict__ boxes,
                     const float* __restrict__ w1,     // ld 2052, wg at col 2048
                     const float* __restrict__ w2,
                     const float* __restrict__ b2,
                     float* __restrict__ rel)
{
    __shared__ float p1s[4][HREP];
    __shared__ float w2s[HREP];
    __shared__ float wgs[HREP][4];
    __shared__ float bxi[4][4];
    const int j = threadIdx.x;        // 512
    const int i0 = blockIdx.x * 4;

    for (int t = j; t < 4 * HREP; t += 512)
        p1s[t >> 8][t & 255] = g_p1[(size_t)(i0 + (t >> 8)) * HREP + (t & 255)];
    if (j < HREP) w2s[j] = w2[j];
    for (int t = j; t < HREP * 4; t += 512)
        wgs[t >> 2][t & 3] = w1[(size_t)(t >> 2) * 2052 + 2048 + (t & 3)];
    if (j < 16) bxi[j >> 2][j & 3] = boxes[(i0 + (j >> 2)) * 4 + (j & 3)];
    __syncthreads();

    const float bj0 = boxes[j * 4 + 0], bj1 = boxes[j * 4 + 1];
    const float bj2 = boxes[j * 4 + 2], bj3 = boxes[j * 4 + 3];
    float gp[4][4];
#pragma unroll
    for (int i = 0; i < 4; i++) {
        gp[i][0] = fabsf(bxi[i][0] - bj0);
        gp[i][1] = fabsf(bxi[i][1] - bj1);
        gp[i][2] = fabsf(bxi[i][2] - bj2);
        gp[i][3] = fabsf(bxi[i][3] - bj3);
    }
    float acc[4] = {0.f, 0.f, 0.f, 0.f};
#pragma unroll 4
    for (int h = 0; h < HREP; h++) {
        const float p2v = g_p2t[h * N + j];
        const float wv  = w2s[h];
        const float wg0 = wgs[h][0], wg1 = wgs[h][1], wg2 = wgs[h][2], wg3 = wgs[h][3];
#pragma unroll
        for (int i = 0; i < 4; i++) {
            float v = p1s[i][h] + p2v
                    + gp[i][0] * wg0 + gp[i][1] * wg1 + gp[i][2] * wg2 + gp[i][3] * wg3;
            acc[i] += fmaxf(v, 0.f) * wv;
        }
    }
    const float bb = b2[0];
#pragma unroll
    for (int i = 0; i < 4; i++)
        rel[(size_t)(i0 + i) * N + j] = acc[i] + bb;
}

// ================= top-(k+1) per row (1 warp/row), drop rank-1 ===================
__global__ void topk_warp(const float* __restrict__ rel)
{
    const int i = blockIdx.x;
    const int lane = threadIdx.x;     // 32
    float v[16];
#pragma unroll
    for (int q = 0; q < 16; q++)
        v[q] = rel[(size_t)i * N + q * 32 + lane];

    for (int r = 0; r < KNBR + 1; r++) {
        float bv = -INFINITY; int bidx = 0x7fffffff;
#pragma unroll
        for (int q = 0; q < 16; q++) {
            if (v[q] > bv) { bv = v[q]; bidx = q * 32 + lane; }
        }
#pragma unroll
        for (int o = 16; o > 0; o >>= 1) {
            float ov = __shfl_down_sync(0xffffffffu, bv, o);
            int   oi = __shfl_down_sync(0xffffffffu, bidx, o);
            if (ov > bv || (ov == bv && oi < bidx)) { bv = ov; bidx = oi; }
        }
        bidx = __shfl_sync(0xffffffffu, bidx, 0);
        if (r > 0 && lane == 0) g_nbrs[i * KNBR + r - 1] = bidx;
        if ((bidx & 31) == lane) v[bidx >> 5] = -INFINITY;
    }
}

// ================= adjacency: warp-ballot per dst (ascending row order) ==========
__global__ void adj_ballot()
{
    const int d = blockIdx.x;
    const int lane = threadIdx.x;     // 32
    int c = 0;
    for (int base = 0; base < N; base += 32) {
        int row = base + lane;
        bool m = false;
#pragma unroll
        for (int jj = 0; jj < KNBR; jj++) m |= (g_nbrs[row * KNBR + jj] == d);
        unsigned msk = __ballot_sync(0xffffffffu, m);
        if (m) {
            int pos = c + __popc(msk & ((1u << lane) - 1u));
            g_adj[d * MAXDEG + pos] = row;
        }
        c += __popc(msk);
    }
    if (lane == 0) { g_adj[d * MAXDEG + c] = d; g_cnt[d] = c + 1; }
}

// ================= attention projections ==========================================
__global__ void aproj1(const float* __restrict__ asrc, const float* __restrict__ adst)
{
    const int n = blockIdx.x;
    const int w = threadIdx.y;
    const int lane = threadIdx.x;
    float s = 0.f, dsum = 0.f;
    for (int f = lane; f < HID; f += 32) {
        float hv = g_h[(size_t)n * 1024 + w * HID + f];
        s    += hv * asrc[w * HID + f];
        dsum += hv * adst[w * HID + f];
    }
#pragma unroll
    for (int o = 16; o > 0; o >>= 1) {
        s    += __shfl_xor_sync(0xffffffffu, s, o);
        dsum += __shfl_xor_sync(0xffffffffu, dsum, o);
    }
    if (lane == 0) { g_as1[n * HEADS + w] = s; g_ad1[n * HEADS + w] = dsum; }
}

__global__ void aproj2(const float* __restrict__ asrc, const float* __restrict__ adst)
{
    const int n = blockIdx.x;
    const int lane = threadIdx.x;
    float s = 0.f, dsum = 0.f;
    for (int f = lane; f < NCLS; f += 32) {
        float v = g_h2[n * NCLS + f];
        s    += v * asrc[f];
        dsum += v * adst[f];
    }
#pragma unroll
    for (int o = 16; o > 0; o >>= 1) {
        s    += __shfl_xor_sync(0xffffffffu, s, o);
        dsum += __shfl_xor_sync(0xffffffffu, dsum, o);
    }
    if (lane == 0) { g_as2[n] = s; g_ad2[n] = dsum; }
}

// ================= GAT1: fused alpha + aggregation + bias + relu =================
__global__ void gat1_fused(const float* __restrict__ bias)
{
    __shared__ int   srcs[MAXDEG];
    __shared__ float al[MAXDEG * HEADS];
    const int d = blockIdx.x, t = threadIdx.x;   // 1024
    const int cnt = g_cnt[d];
    for (int x = t; x < cnt; x += 1024) srcs[x] = g_adj[d * MAXDEG + x];
    __syncthreads();

    for (int idx = t; idx < cnt * HEADS; idx += 1024) {
        int x = idx >> 2, hd = idx & 3;
        float a = g_as1[srcs[x] * HEADS + hd] + g_ad1[d * HEADS + hd];
        al[idx] = a > 0.f ? a : 0.2f * a;
    }
    __syncthreads();

    const int w = t >> 5, lane = t & 31;
    if (w < HEADS) {
        float lm = -INFINITY;
        for (int x = lane; x < cnt; x += 32) lm = fmaxf(lm, al[x * HEADS + w]);
#pragma unroll
        for (int o = 16; o > 0; o >>= 1)
            lm = fmaxf(lm, __shfl_xor_sync(0xffffffffu, lm, o));
        float ls = 0.f;
        for (int x = lane; x < cnt; x += 32) {
            float e = expf(al[x * HEADS + w] - lm);
            al[x * HEADS + w] = e;
            ls += e;
        }
#pragma unroll
        for (int o = 16; o > 0; o >>= 1)
            ls += __shfl_xor_sync(0xffffffffu, ls, o);
        const float inv = 1.f / (ls + 1e-16f);
        for (int x = lane; x < cnt; x += 32)
            al[x * HEADS + w] *= inv;
    }
    __syncthreads();

    const int hd = t >> 8;
    float acc = 0.f;
    for (int x = 0; x < cnt; x++)
        acc += al[x * HEADS + hd] * g_h[(size_t)srcs[x] * 1024 + t];
    float o = acc + bias[t];
    g_h1[(size_t)d * 1024 + t] = fmaxf(o, 0.f);
}

// ================= GAT2: fused alpha + aggregation + bias + softmax ==============
__global__ void gat2_fused(const float* __restrict__ bias, float* __restrict__ out)
{
    __shared__ int   srcs[MAXDEG];
    __shared__ float al[MAXDEG];
    __shared__ float lrow[NCLS];
    __shared__ float red[128];
    const int d = blockIdx.x, t = threadIdx.x;   // 128
    const int cnt = g_cnt[d];
    for (int x = t; x < cnt; x += 128) srcs[x] = g_adj[d * MAXDEG + x];
    __syncthreads();

    if (t < 32) {
        const float add = g_ad2[d];
        float lm = -INFINITY;
        for (int x = t; x < cnt; x += 32) {
            float a = g_as2[srcs[x]] + add;
            float e = a > 0.f ? a : 0.2f * a;
            al[x] = e;
            lm = fmaxf(lm, e);
        }
#pragma unroll
        for (int o = 16; o > 0; o >>= 1)
            lm = fmaxf(lm, __shfl_xor_sync(0xffffffffu, lm, o));
        float ls = 0.f;
        for (int x = t; x < cnt; x += 32) {
            float e = expf(al[x] - lm);
            al[x] = e;
            ls += e;
        }
#pragma unroll
        for (int o = 16; o > 0; o >>= 1)
            ls += __shfl_xor_sync(0xffffffffu, ls, o);
        const float inv = 1.f / (ls + 1e-16f);
        for (int x = t; x < cnt; x += 32)
            al[x] *= inv;
    }
    __syncthreads();

    if (t < NCLS) {
        float acc = 0.f;
        for (int x = 0; x < cnt; x++)
            acc += al[x] * g_h2[srcs[x] * NCLS + t];
        float lg = acc + bias[t];
        lrow[t] = lg;
        out[(size_t)d * NCLS + t] = lg;          // logits
    }
    __syncthreads();

    float v = (t < NCLS) ? lrow[t] : -INFINITY;
    red[t] = v; __syncthreads();
    for (int s = 64; s > 0; s >>= 1) {
        if (t < s) red[t] = fmaxf(red[t], red[t + s]);
        __syncthreads();
    }
    const float mx = red[0]; __syncthreads();
    float e = (t < NCLS) ? expf(lrow[t] - mx) : 0.f;
    red[t] = e; __syncthreads();
    for (int s = 64; s > 0; s >>= 1) {
        if (t < s) red[t] += red[t + s];
        __syncthreads();
    }
    const float ssum = red[0];
    if (t < NCLS)
        out[(size_t)N * NCLS + (size_t)d * NCLS + t] = e / ssum;   // probs
}

// ================= launch =========================================================
extern "C" void kernel_launch(void* const* d_in, const int* in_sizes, int n_in,
                              void* d_out, int out_size)
{
    (void)in_sizes; (void)n_in; (void)out_size;
    const float* feats     = (const float*)d_in[0];
    const float* boxes     = (const float*)d_in[1];
    const float* repn_w1   = (const float*)d_in[2];
    const float* repn_b1   = (const float*)d_in[3];
    const float* repn_w2   = (const float*)d_in[4];
    const float* repn_b2   = (const float*)d_in[5];
    const float* gat1_w    = (const float*)d_in[6];
    const float* gat1_asrc = (const float*)d_in[7];
    const float* gat1_adst = (const float*)d_in[8];
    const float* gat1_b    = (const float*)d_in[9];
    const float* gat2_w    = (const float*)d_in[10];
    const float* gat2_asrc = (const float*)d_in[11];
    const float* gat2_adst = (const float*)d_in[12];
    const float* gat2_b    = (const float*)d_in[13];
    float* out = (float*)d_out;
    float* rel_out = out + 2 * N * NCLS;

    gemm_nt_fused<<<dim3(16, 8), 256>>>(feats, repn_w1, repn_b1);   // g_p1 + g_p2t
    gemm_nn_gat1<<<dim3(8, 16), dim3(16, 16)>>>(feats, boxes, gat1_w); // g_h
    rel4<<<128, 512>>>(boxes, repn_w1, repn_w2, repn_b2, rel_out);
    topk_warp<<<N, 32>>>(rel_out);
    adj_ballot<<<N, 32>>>();
    aproj1<<<N, dim3(32, 4)>>>(gat1_asrc, gat1_adst);
    gat1_fused<<<N, 1024>>>(gat1_b);
    gemm_gat2<<<dim3(6, 32), dim3(16, 16)>>>(gat2_w);               // g_h2
    aproj2<<<N, 32>>>(gat2_asrc, gat2_adst);
    gat2_fused<<<N, 128>>>(gat2_b, out);
}

// round 5
// speedup vs baseline: 2.2558x; 1.0017x over previous
#include <cuda_runtime.h>
#include <math.h>

#define N 512
#define C 1024
#define HREP 256
#define HID 256
#define HEADS 4
#define NCLS 91
#define KNBR 5
#define MAXDEG 520

// ---------------- scratch (device globals; NEVER passed as launch args) ----------
__device__ float g_p1[N * HREP];           // p1 + b1, [n][h]
__device__ float g_p2t[HREP * N];          // p2 transposed, [h][n]
__device__ int   g_nbrs[N * KNBR];
__device__ int   g_adj[N * MAXDEG];
__device__ int   g_cnt[N];
__device__ float g_h[N * 1024];            // gat1 linear out
__device__ float g_as1[N * HEADS];
__device__ float g_ad1[N * HEADS];
__device__ float g_h1[N * 1024];           // relu(gat1 out + b)
__device__ float g_h2[N * NCLS];           // gat2 linear out
__device__ float g_as2[N];
__device__ float g_ad2[N];

// f32x2 helpers -------------------------------------------------------------------
__device__ __forceinline__ unsigned long long dup2(float a) {
    unsigned long long d;
    asm("mov.b64 %0, {%1, %1};" : "=l"(d) : "f"(a));
    return d;
}
__device__ __forceinline__ void fma2(unsigned long long& acc, unsigned long long a,
                                     unsigned long long b) {
    asm("fma.rn.f32x2 %0, %1, %2, %0;" : "+l"(acc) : "l"(a), "l"(b));
}
__device__ __forceinline__ void unpack2(unsigned long long v, float& lo, float& hi) {
    asm("mov.b64 {%0, %1}, %2;" : "=f"(lo), "=f"(hi) : "l"(v));
}

// ================= fused p1/p2 NT GEMM, 32x64 tile, 2x4/thread, f32x2 ============
// blockIdx.y < 4 : p1 block  -> g_p1[n*256 + h] = feats·wf1[h] + b1[h]
// blockIdx.y >= 4: p2t block -> g_p2t[h*512 + n] = feats·wf2[h]
__global__ void gemm_nt_fused(const float* __restrict__ A, const float* __restrict__ W,
                              const float* __restrict__ bias)
{
    __shared__ float As[16][32];
    __shared__ float Ws[16][64];
    const int tid = threadIdx.x;                 // 256
    const int n0 = blockIdx.x * 32;
    const int cb = blockIdx.y;
    const bool p2mode = (cb >= 4);
    const int h0 = (p2mode ? cb - 4 : cb) * 64;
    const int woff = p2mode ? 1024 : 0;
    const int ar = tid >> 3, ak = (tid & 7) * 2;
    const int wr = tid >> 2, wk = (tid & 3) * 4;
    const int tx = tid & 15, ty = tid >> 4;

    unsigned long long acc2[2][2];               // [row][col-pair]
#pragma unroll
    for (int i = 0; i < 2; i++)
#pragma unroll
        for (int j = 0; j < 2; j++) acc2[i][j] = 0ULL;

    for (int k0 = 0; k0 < C; k0 += 16) {
        float2 av = *reinterpret_cast<const float2*>(&A[(size_t)(n0 + ar) * C + k0 + ak]);
        As[ak][ar] = av.x; As[ak + 1][ar] = av.y;
        float4 wv = *reinterpret_cast<const float4*>(&W[(size_t)(h0 + wr) * 2052 + woff + k0 + wk]);
        Ws[wk + 0][wr] = wv.x; Ws[wk + 1][wr] = wv.y;
        Ws[wk + 2][wr] = wv.z; Ws[wk + 3][wr] = wv.w;
        __syncthreads();
#pragma unroll
        for (int kk = 0; kk < 16; kk++) {
            const unsigned long long* bp =
                reinterpret_cast<const unsigned long long*>(&Ws[kk][tx * 4]);
            unsigned long long b0 = bp[0], b1 = bp[1];
            unsigned long long a0 = dup2(As[kk][ty * 2 + 0]);
            unsigned long long a1 = dup2(As[kk][ty * 2 + 1]);
            fma2(acc2[0][0], a0, b0); fma2(acc2[0][1], a0, b1);
            fma2(acc2[1][0], a1, b0); fma2(acc2[1][1], a1, b1);
        }
        __syncthreads();
    }

#pragma unroll
    for (int i = 0; i < 2; i++) {
        const int n = n0 + ty * 2 + i;
        float c0, c1, c2, c3;
        unpack2(acc2[i][0], c0, c1);
        unpack2(acc2[i][1], c2, c3);
        float cv[4] = {c0, c1, c2, c3};
#pragma unroll
        for (int j = 0; j < 4; j++) {
            const int h = h0 + tx * 4 + j;
            const float v = cv[j] + (p2mode ? 0.f : bias[h]);
            if (p2mode) g_p2t[(size_t)h * N + n] = v;
            else        g_p1[(size_t)n * HREP + h] = v;
        }
    }
}

// ================= GAT1 linear: g_h = [feats|geom](512x1028) @ gat1_w, f32x2 =====
__global__ void gemm_nn_gat1(const float* __restrict__ A, const float* __restrict__ boxes,
                             const float* __restrict__ B)
{
    __shared__ float As[16][64];
    __shared__ float Bs[16][64];
    const int tx = threadIdx.x, ty = threadIdx.y;
    const int tid = ty * 16 + tx;
    const int n0 = blockIdx.x * 64, o0 = blockIdx.y * 64;
    const int lr = tid >> 2;
    const int lk = (tid & 3) * 4;
    const int kb = tid >> 4;
    const int cg = (tid & 15) * 4;

    unsigned long long acc2[4][2];               // [row][col-pair]
#pragma unroll
    for (int i = 0; i < 4; i++)
#pragma unroll
        for (int j = 0; j < 2; j++) acc2[i][j] = 0ULL;

    for (int k0 = 0; k0 < 1024; k0 += 16) {
        float4 av = *reinterpret_cast<const float4*>(&A[(size_t)(n0 + lr) * 1024 + k0 + lk]);
        As[lk + 0][lr] = av.x; As[lk + 1][lr] = av.y;
        As[lk + 2][lr] = av.z; As[lk + 3][lr] = av.w;
        float4 bv = *reinterpret_cast<const float4*>(&B[(size_t)(k0 + kb) * 1024 + o0 + cg]);
        *reinterpret_cast<float4*>(&Bs[kb][cg]) = bv;
        __syncthreads();
#pragma unroll
        for (int kk = 0; kk < 16; kk++) {
            const unsigned long long* bp =
                reinterpret_cast<const unsigned long long*>(&Bs[kk][tx * 4]);
            unsigned long long b0 = bp[0], b1 = bp[1];
            float4 a4 = *reinterpret_cast<float4*>(&As[kk][ty * 4]);
            unsigned long long a0 = dup2(a4.x), a1 = dup2(a4.y);
            unsigned long long a2 = dup2(a4.z), a3 = dup2(a4.w);
            fma2(acc2[0][0], a0, b0); fma2(acc2[0][1], a0, b1);
            fma2(acc2[1][0], a1, b0); fma2(acc2[1][1], a1, b1);
            fma2(acc2[2][0], a2, b0); fma2(acc2[2][1], a2, b1);
            fma2(acc2[3][0], a3, b0); fma2(acc2[3][1], a3, b1);
        }
        __syncthreads();
    }

#pragma unroll
    for (int i = 0; i < 4; i++) {
        const int n = n0 + ty * 4 + i;
        const float b0 = boxes[n * 4 + 0], b1 = boxes[n * 4 + 1];
        const float b2v = boxes[n * 4 + 2], b3 = boxes[n * 4 + 3];
        const float gm0 = b0 / 800.f, gm1 = b1 / 800.f;
        const float gm2 = (b2v - b0) / 800.f, gm3 = (b3 - b1) / 800.f;
        float c0, c1, c2, c3;
        unpack2(acc2[i][0], c0, c1);
        unpack2(acc2[i][1], c2, c3);
        float cv[4] = {c0, c1, c2, c3};
#pragma unroll
        for (int j = 0; j < 4; j++) {
            const int col = o0 + tx * 4 + j;
            float v = cv[j]
                    + gm0 * B[(size_t)1024 * 1024 + col] + gm1 * B[(size_t)1025 * 1024 + col]
                    + gm2 * B[(size_t)1026 * 1024 + col] + gm3 * B[(size_t)1027 * 1024 + col];
            g_h[(size_t)n * 1024 + col] = v;
        }
    }
}

// ================= GAT2 linear: g_h2 = g_h1(512x1024) @ gat2_w(1024x91) ==========
__global__ void gemm_gat2(const float* __restrict__ B)
{
    __shared__ float As[16][17];
    __shared__ float Bs[16][17];
    const int tx = threadIdx.x, ty = threadIdx.y;
    const int n = blockIdx.y * 16 + ty;
    const int o = blockIdx.x * 16 + tx;
    float acc = 0.f;
    for (int k0 = 0; k0 < 1024; k0 += 16) {
        As[ty][tx] = g_h1[(size_t)n * 1024 + k0 + tx];
        Bs[ty][tx] = (o < NCLS) ? B[(size_t)(k0 + ty) * NCLS + o] : 0.f;
        __syncthreads();
#pragma unroll
        for (int kk = 0; kk < 16; kk++)
            acc += As[ty][kk] * Bs[kk][tx];
        __syncthreads();
    }
    if (o < NCLS)
        g_h2[(size_t)n * NCLS + o] = acc;
}

// ================= rel with 4-row i-tiling ========================================
__global__ void rel4(const float* __restrict__ boxes,
                     const float* __restrict__ w1,     // ld 2052, wg at col 2048
                     const float* __restrict__ w2,
                     const float* __restrict__ b2,
                     float* __restrict__ rel)
{
    __shared__ float p1s[4][HREP];
    __shared__ float w2s[HREP];
    __shared__ float wgs[HREP][4];
    __shared__ float bxi[4][4];
    const int j = threadIdx.x;        // 512
    const int i0 = blockIdx.x * 4;

    for (int t = j; t < 4 * HREP; t += 512)
        p1s[t >> 8][t & 255] = g_p1[(size_t)(i0 + (t >> 8)) * HREP + (t & 255)];
    if (j < HREP) w2s[j] = w2[j];
    for (int t = j; t < HREP * 4; t += 512)
        wgs[t >> 2][t & 3] = w1[(size_t)(t >> 2) * 2052 + 2048 + (t & 3)];
    if (j < 16) bxi[j >> 2][j & 3] = boxes[(i0 + (j >> 2)) * 4 + (j & 3)];
    __syncthreads();

    const float bj0 = boxes[j * 4 + 0], bj1 = boxes[j * 4 + 1];
    const float bj2 = boxes[j * 4 + 2], bj3 = boxes[j * 4 + 3];
    float gp[4][4];
#pragma unroll
    for (int i = 0; i < 4; i++) {
        gp[i][0] = fabsf(bxi[i][0] - bj0);
        gp[i][1] = fabsf(bxi[i][1] - bj1);
        gp[i][2] = fabsf(bxi[i][2] - bj2);
        gp[i][3] = fabsf(bxi[i][3] - bj3);
    }
    float acc[4] = {0.f, 0.f, 0.f, 0.f};
#pragma unroll 4
    for (int h = 0; h < HREP; h++) {
        const float p2v = g_p2t[h * N + j];
        const float wv  = w2s[h];
        const float wg0 = wgs[h][0], wg1 = wgs[h][1], wg2 = wgs[h][2], wg3 = wgs[h][3];
#pragma unroll
        for (int i = 0; i < 4; i++) {
            float v = p1s[i][h] + p2v
                    + gp[i][0] * wg0 + gp[i][1] * wg1 + gp[i][2] * wg2 + gp[i][3] * wg3;
            acc[i] += fmaxf(v, 0.f) * wv;
        }
    }
    const float bb = b2[0];
#pragma unroll
    for (int i = 0; i < 4; i++)
        rel[(size_t)(i0 + i) * N + j] = acc[i] + bb;
}

// ================= top-(k+1) per row (1 warp/row), drop rank-1 ===================
__global__ void topk_warp(const float* __restrict__ rel)
{
    const int i = blockIdx.x;
    const int lane = threadIdx.x;     // 32
    float v[16];
#pragma unroll
    for (int q = 0; q < 16; q++)
        v[q] = rel[(size_t)i * N + q * 32 + lane];

    for (int r = 0; r < KNBR + 1; r++) {
        float bv = -INFINITY; int bidx = 0x7fffffff;
#pragma unroll
        for (int q = 0; q < 16; q++) {
            if (v[q] > bv) { bv = v[q]; bidx = q * 32 + lane; }
        }
#pragma unroll
        for (int o = 16; o > 0; o >>= 1) {
            float ov = __shfl_down_sync(0xffffffffu, bv, o);
            int   oi = __shfl_down_sync(0xffffffffu, bidx, o);
            if (ov > bv || (ov == bv && oi < bidx)) { bv = ov; bidx = oi; }
        }
        bidx = __shfl_sync(0xffffffffu, bidx, 0);
        if (r > 0 && lane == 0) g_nbrs[i * KNBR + r - 1] = bidx;
        if ((bidx & 31) == lane) v[bidx >> 5] = -INFINITY;
    }
}

// ================= adjacency: warp-ballot per dst (ascending row order) ==========
__global__ void adj_ballot()
{
    const int d = blockIdx.x;
    const int lane = threadIdx.x;     // 32
    int c = 0;
    for (int base = 0; base < N; base += 32) {
        int row = base + lane;
        bool m = false;
#pragma unroll
        for (int jj = 0; jj < KNBR; jj++) m |= (g_nbrs[row * KNBR + jj] == d);
        unsigned msk = __ballot_sync(0xffffffffu, m);
        if (m) {
            int pos = c + __popc(msk & ((1u << lane) - 1u));
            g_adj[d * MAXDEG + pos] = row;
        }
        c += __popc(msk);
    }
    if (lane == 0) { g_adj[d * MAXDEG + c] = d; g_cnt[d] = c + 1; }
}

// ================= attention projections ==========================================
__global__ void aproj1(const float* __restrict__ asrc, const float* __restrict__ adst)
{
    const int n = blockIdx.x;
    const int w = threadIdx.y;
    const int lane = threadIdx.x;
    float s = 0.f, dsum = 0.f;
    for (int f = lane; f < HID; f += 32) {
        float hv = g_h[(size_t)n * 1024 + w * HID + f];
        s    += hv * asrc[w * HID + f];
        dsum += hv * adst[w * HID + f];
    }
#pragma unroll
    for (int o = 16; o > 0; o >>= 1) {
        s    += __shfl_xor_sync(0xffffffffu, s, o);
        dsum += __shfl_xor_sync(0xffffffffu, dsum, o);
    }
    if (lane == 0) { g_as1[n * HEADS + w] = s; g_ad1[n * HEADS + w] = dsum; }
}

__global__ void aproj2(const float* __restrict__ asrc, const float* __restrict__ adst)
{
    const int n = blockIdx.x;
    const int lane = threadIdx.x;
    float s = 0.f, dsum = 0.f;
    for (int f = lane; f < NCLS; f += 32) {
        float v = g_h2[n * NCLS + f];
        s    += v * asrc[f];
        dsum += v * adst[f];
    }
#pragma unroll
    for (int o = 16; o > 0; o >>= 1) {
        s    += __shfl_xor_sync(0xffffffffu, s, o);
        dsum += __shfl_xor_sync(0xffffffffu, dsum, o);
    }
    if (lane == 0) { g_as2[n] = s; g_ad2[n] = dsum; }
}

// ================= GAT1: fused alpha + aggregation + bias + relu =================
__global__ void gat1_fused(const float* __restrict__ bias)
{
    __shared__ int   srcs[MAXDEG];
    __shared__ float al[MAXDEG * HEADS];
    const int d = blockIdx.x, t = threadIdx.x;   // 1024
    const int cnt = g_cnt[d];
    for (int x = t; x < cnt; x += 1024) srcs[x] = g_adj[d * MAXDEG + x];
    __syncthreads();

    for (int idx = t; idx < cnt * HEADS; idx += 1024) {
        int x = idx >> 2, hd = idx & 3;
        float a = g_as1[srcs[x] * HEADS + hd] + g_ad1[d * HEADS + hd];
        al[idx] = a > 0.f ? a : 0.2f * a;
    }
    __syncthreads();

    const int w = t >> 5, lane = t & 31;
    if (w < HEADS) {
        float lm = -INFINITY;
        for (int x = lane; x < cnt; x += 32) lm = fmaxf(lm, al[x * HEADS + w]);
#pragma unroll
        for (int o = 16; o > 0; o >>= 1)
            lm = fmaxf(lm, __shfl_xor_sync(0xffffffffu, lm, o));
        float ls = 0.f;
        for (int x = lane; x < cnt; x += 32) {
            float e = expf(al[x * HEADS + w] - lm);
            al[x * HEADS + w] = e;
            ls += e;
        }
#pragma unroll
        for (int o = 16; o > 0; o >>= 1)
            ls += __shfl_xor_sync(0xffffffffu, ls, o);
        const float inv = 1.f / (ls + 1e-16f);
        for (int x = lane; x < cnt; x += 32)
            al[x * HEADS + w] *= inv;
    }
    __syncthreads();

    const int hd = t >> 8;
    float acc = 0.f;
    for (int x = 0; x < cnt; x++)
        acc += al[x * HEADS + hd] * g_h[(size_t)srcs[x] * 1024 + t];
    float o = acc + bias[t];
    g_h1[(size_t)d * 1024 + t] = fmaxf(o, 0.f);
}

// ================= GAT2: fused alpha + aggregation + bias + softmax ==============
__global__ void gat2_fused(const float* __restrict__ bias, float* __restrict__ out)
{
    __shared__ int   srcs[MAXDEG];
    __shared__ float al[MAXDEG];
    __shared__ float lrow[NCLS];
    __shared__ float red[128];
    const int d = blockIdx.x, t = threadIdx.x;   // 128
    const int cnt = g_cnt[d];
    for (int x = t; x < cnt; x += 128) srcs[x] = g_adj[d * MAXDEG + x];
    __syncthreads();

    if (t < 32) {
        const float add = g_ad2[d];
        float lm = -INFINITY;
        for (int x = t; x < cnt; x += 32) {
            float a = g_as2[srcs[x]] + add;
            float e = a > 0.f ? a : 0.2f * a;
            al[x] = e;
            lm = fmaxf(lm, e);
        }
#pragma unroll
        for (int o = 16; o > 0; o >>= 1)
            lm = fmaxf(lm, __shfl_xor_sync(0xffffffffu, lm, o));
        float ls = 0.f;
        for (int x = t; x < cnt; x += 32) {
            float e = expf(al[x] - lm);
            al[x] = e;
            ls += e;
        }
#pragma unroll
        for (int o = 16; o > 0; o >>= 1)
            ls += __shfl_xor_sync(0xffffffffu, ls, o);
        const float inv = 1.f / (ls + 1e-16f);
        for (int x = t; x < cnt; x += 32)
            al[x] *= inv;
    }
    __syncthreads();

    if (t < NCLS) {
        float acc = 0.f;
        for (int x = 0; x < cnt; x++)
            acc += al[x] * g_h2[srcs[x] * NCLS + t];
        float lg = acc + bias[t];
        lrow[t] = lg;
        out[(size_t)d * NCLS + t] = lg;          // logits
    }
    __syncthreads();

    float v = (t < NCLS) ? lrow[t] : -INFINITY;
    red[t] = v; __syncthreads();
    for (int s = 64; s > 0; s >>= 1) {
        if (t < s) red[t] = fmaxf(red[t], red[t + s]);
        __syncthreads();
    }
    const float mx = red[0]; __syncthreads();
    float e = (t < NCLS) ? expf(lrow[t] - mx) : 0.f;
    red[t] = e; __syncthreads();
    for (int s = 64; s > 0; s >>= 1) {
        if (t < s) red[t] += red[t + s];
        __syncthreads();
    }
    const float ssum = red[0];
    if (t < NCLS)
        out[(size_t)N * NCLS + (size_t)d * NCLS + t] = e / ssum;   // probs
}

// ================= stream/event infra (created at static init, never freed) ======
struct SideStream {
    cudaStream_t s2;
    cudaEvent_t eFork, eJoin;
    SideStream() {
        cudaStreamCreateWithFlags(&s2, cudaStreamNonBlocking);
        cudaEventCreateWithFlags(&eFork, cudaEventDisableTiming);
        cudaEventCreateWithFlags(&eJoin, cudaEventDisableTiming);
    }
};
static SideStream g_ss;

// ================= launch =========================================================
extern "C" void kernel_launch(void* const* d_in, const int* in_sizes, int n_in,
                              void* d_out, int out_size)
{
    (void)in_sizes; (void)n_in; (void)out_size;
    const float* feats     = (const float*)d_in[0];
    const float* boxes     = (const float*)d_in[1];
    const float* repn_w1   = (const float*)d_in[2];
    const float* repn_b1   = (const float*)d_in[3];
    const float* repn_w2   = (const float*)d_in[4];
    const float* repn_b2   = (const float*)d_in[5];
    const float* gat1_w    = (const float*)d_in[6];
    const float* gat1_asrc = (const float*)d_in[7];
    const float* gat1_adst = (const float*)d_in[8];
    const float* gat1_b    = (const float*)d_in[9];
    const float* gat2_w    = (const float*)d_in[10];
    const float* gat2_asrc = (const float*)d_in[11];
    const float* gat2_adst = (const float*)d_in[12];
    const float* gat2_b    = (const float*)d_in[13];
    float* out = (float*)d_out;
    float* rel_out = out + 2 * N * NCLS;

    // ---- fork: GAT1 linear branch on side stream ----
    cudaEventRecord(g_ss.eFork, 0);
    cudaStreamWaitEvent(g_ss.s2, g_ss.eFork, 0);
    gemm_nn_gat1<<<dim3(8, 16), dim3(16, 16), 0, g_ss.s2>>>(feats, boxes, gat1_w);
    aproj1<<<N, dim3(32, 4), 0, g_ss.s2>>>(gat1_asrc, gat1_adst);
    cudaEventRecord(g_ss.eJoin, g_ss.s2);

    // ---- main chain: rel branch ----
    gemm_nt_fused<<<dim3(16, 8), 256>>>(feats, repn_w1, repn_b1);   // g_p1 + g_p2t
    rel4<<<128, 512>>>(boxes, repn_w1, repn_w2, repn_b2, rel_out);
    topk_warp<<<N, 32>>>(rel_out);
    adj_ballot<<<N, 32>>>();

    // ---- join ----
    cudaStreamWaitEvent(0, g_ss.eJoin, 0);
    gat1_fused<<<N, 1024>>>(gat1_b);
    gemm_gat2<<<dim3(6, 32), dim3(16, 16)>>>(gat2_w);               // g_h2
    aproj2<<<N, 32>>>(gat2_asrc, gat2_adst);
    gat2_fused<<<N, 128>>>(gat2_b, out);
}